// round 13
// baseline (speedup 1.0000x reference)
#include <cuda_runtime.h>
#include <math.h>

#define BATCH   128
#define M_NODES 64
#define SEQROWS (BATCH * M_NODES)   // 8192
#define LATENT  256
#define HIDDEN  512
#define G3      1536
#define NPAIR   2016

typedef unsigned long long ull;

// ---------------- scratch ----------------
__device__ float g_x   [SEQROWS * 512];
__device__ float g_seq [SEQROWS * LATENT];
__device__ float g_gi  [SEQROWS * G3];
__device__ float g_hs0 [SEQROWS * HIDDEN];
__device__ float g_hs1 [SEQROWS * HIDDEN];
__device__ float g_node[SEQROWS * HIDDEN];
__device__ float g_ca  [SEQROWS * HIDDEN];
__device__ float g_cb  [SEQROWS * HIDDEN];
__device__ float g_ht  [2][HIDDEN * BATCH];   // transposed h ping-pong: [k][b]
__device__ int   g_ctr [8];

// ---------------- helpers ----------------
__device__ __forceinline__ float sigm(float x) {
    return 0.5f * tanhf(0.5f * x) + 0.5f;
}
__device__ __forceinline__ ull ffma2(ull a, ull b, ull c) {
    ull d;
    asm("fma.rn.f32x2 %0, %1, %2, %3;" : "=l"(d) : "l"(a), "l"(b), "l"(c));
    return d;
}
__device__ __forceinline__ ull fadd2(ull a, ull b) {
    ull d;
    asm("add.rn.f32x2 %0, %1, %2;" : "=l"(d) : "l"(a), "l"(b));
    return d;
}
__device__ __forceinline__ ull dup2(float x) {
    ull r;
    asm("mov.b64 %0, {%1, %1};" : "=l"(r) : "f"(x));
    return r;
}
__device__ __forceinline__ void unpack2(ull v, float& lo, float& hi) {
    asm("mov.b64 {%0, %1}, %2;" : "=f"(lo), "=f"(hi) : "l"(v));
}

// ---------------- counter reset (also shifts launch order so ncu -s 5 hits the GRU) ----
__global__ void zero_ctr()
{
    if (threadIdx.x < 8) g_ctr[threadIdx.x] = 0;
}

// ---------------- build x = concat(z+pe, emb), time-major rows ----------------
__global__ void build_x(const float* __restrict__ z, const float* __restrict__ pe,
                        const float* __restrict__ emb, float* __restrict__ x)
{
    int idx = blockIdx.x * blockDim.x + threadIdx.x;
    int c = idx & 511;
    int r = idx >> 9;
    int b = r & 127;
    int t = r >> 7;
    float v;
    if (c < 256) v = z[b * 256 + c] + pe[t * 256 + c];
    else         v = emb[t * 256 + (c - 256)];
    x[idx] = v;
}

// ---------------- masking ----------------
__global__ void mask_kernel(float* __restrict__ buf, const int* __restrict__ n_nodes,
                            int logw)
{
    int idx = blockIdx.x * blockDim.x + threadIdx.x;
    int r = idx >> logw;
    int b = r & 127;
    int t = r >> 7;
    if (t >= n_nodes[b]) buf[idx] = 0.0f;
}

// ---------------- SGEMM: C[M][N] = A[M][K] @ B[N][K]^T (+bias) ----------------
__global__ __launch_bounds__(256)
void sgemm2(const float* __restrict__ A, int lda,
            const float* __restrict__ B, int ldb,
            float* __restrict__ C, int ldc,
            const float* __restrict__ bias, int K)
{
    __shared__ float As[8 * 132];
    __shared__ float Bs[8 * 132];
    const int tid = threadIdx.x;
    const int m0 = blockIdx.y * 128;
    const int n0 = blockIdx.x * 128;
    const int arow = tid >> 1;
    const int ak   = (tid & 1) << 2;
    const int tx = tid & 15;
    const int ty = tid >> 4;

    const float* Ap = A + (long)(m0 + arow) * lda + ak;
    const float* Bp = B + (long)(n0 + arow) * ldb + ak;

    float acc[8][8];
    #pragma unroll
    for (int i = 0; i < 8; i++)
        #pragma unroll
        for (int j = 0; j < 8; j++) acc[i][j] = 0.0f;

    float4 pa = *(const float4*)Ap;
    float4 pb = *(const float4*)Bp;
    const int np = K >> 3;
    for (int p = 0; p < np; p++) {
        __syncthreads();
        As[(ak + 0) * 132 + arow] = pa.x;
        As[(ak + 1) * 132 + arow] = pa.y;
        As[(ak + 2) * 132 + arow] = pa.z;
        As[(ak + 3) * 132 + arow] = pa.w;
        Bs[(ak + 0) * 132 + arow] = pb.x;
        Bs[(ak + 1) * 132 + arow] = pb.y;
        Bs[(ak + 2) * 132 + arow] = pb.z;
        Bs[(ak + 3) * 132 + arow] = pb.w;
        __syncthreads();
        if (p + 1 < np) {
            pa = *(const float4*)(Ap + (p + 1) * 8);
            pb = *(const float4*)(Bp + (p + 1) * 8);
        }
        #pragma unroll
        for (int kk = 0; kk < 8; kk++) {
            float4 a0 = *(const float4*)&As[kk * 132 + (ty << 2)];
            float4 a1 = *(const float4*)&As[kk * 132 + 64 + (ty << 2)];
            float4 b0 = *(const float4*)&Bs[kk * 132 + (tx << 2)];
            float4 b1 = *(const float4*)&Bs[kk * 132 + 64 + (tx << 2)];
            float av[8] = {a0.x, a0.y, a0.z, a0.w, a1.x, a1.y, a1.z, a1.w};
            float bv[8] = {b0.x, b0.y, b0.z, b0.w, b1.x, b1.y, b1.z, b1.w};
            #pragma unroll
            for (int i = 0; i < 8; i++)
                #pragma unroll
                for (int j = 0; j < 8; j++)
                    acc[i][j] = fmaf(av[i], bv[j], acc[i][j]);
        }
    }

    #pragma unroll
    for (int i = 0; i < 8; i++) {
        int m = m0 + ((i < 4) ? ((ty << 2) + i) : (64 + (ty << 2) + i - 4));
        #pragma unroll
        for (int jh = 0; jh < 2; jh++) {
            int n = n0 + jh * 64 + (tx << 2);
            float4 v;
            v.x = acc[i][jh * 4 + 0] + (bias ? bias[n + 0] : 0.0f);
            v.y = acc[i][jh * 4 + 1] + (bias ? bias[n + 1] : 0.0f);
            v.z = acc[i][jh * 4 + 2] + (bias ? bias[n + 2] : 0.0f);
            v.w = acc[i][jh * 4 + 3] + (bias ? bias[n + 3] : 0.0f);
            *(float4*)&C[(long)m * ldc + n] = v;
        }
    }
}

// ---------------- persistent GRU, k-split across 8 warps ----------------
// Grid 128 = 16 jt (32 j) x 8 bt (16 b); 256 threads = 8 warps (2/SMSP for
// latency hiding). Warp w covers k in [w*64, (w+1)*64) for the FULL 32j x 16b
// tile; lane = j. w_s[g][k][j ^ (k&31)] resident all 64 steps; h_s transposed
// [k][16 b]. Two-phase cross-warp k-reduction through scratch overlaid on h_s.
#define WS2 (3 * 512 * 32)             // 196608 floats
#define HS2 (512 * 16)                 // 8192 floats
#define GRU_SMEM_BYTES ((WS2 + HS2) * 4)   // 229376

__global__ __launch_bounds__(256, 1)
void gru_persist3(const float* __restrict__ gi_all,   // [64][128][1536]
                  const float* __restrict__ Whh,      // [1536][512]
                  const float* __restrict__ bhh,      // [1536]
                  float* __restrict__ hs_out,         // [64][128][512]
                  float* __restrict__ hbt0,           // [512][128] transposed h
                  float* __restrict__ hbt1,
                  const int* __restrict__ n_nodes,
                  int mask_out)
{
    extern __shared__ float smem[];
    float* w_s = smem;                 // [3][512][32] swizzled
    float* h_s = smem + WS2;           // [512][16]

    const int tid  = threadIdx.x;
    const int lane = tid & 31;         // j within tile
    const int warp = tid >> 5;         // k-eighth owner; also bpair owner
    const int jt = blockIdx.x & 15;
    const int bt = blockIdx.x >> 4;
    const int j0g = jt * 32;
    const int b0  = bt * 16;

    // one-time: Whh -> smem, transposed [g][k][j] with XOR swizzle (conflict-free R/W)
    for (int i = tid; i < WS2; i += 256) {
        int k = i & 511;
        int row = i >> 9;              // 0..95
        int j = row & 31;
        int g = row >> 5;
        w_s[(g * 512 + k) * 32 + (j ^ (k & 31))] = Whh[(g * 512 + j0g + j) * 512 + k];
    }
    for (int i = tid; i < HS2; i += 256) h_s[i] = 0.0f;

    const int jg = j0g + lane;
    const float brj = bhh[jg], bzj = bhh[512 + jg], bnj = bhh[1024 + jg];
    const int bm0 = b0 + 2 * warp;     // my two batches: bm0, bm0+1
    const int nb0 = n_nodes[bm0];
    const int nb1 = n_nodes[bm0 + 1];
    __syncthreads();

    const int k0 = warp * 64;
    const float* wp = w_s + k0 * 32;

    for (int t = 0; t < 64; t++) {
        // prefetch gi for my 2 batches (consumed thousands of cycles later)
        float gir[2], giz[2], gin[2];
        #pragma unroll
        for (int bb = 0; bb < 2; bb++) {
            const float* grow = gi_all + ((long)t * BATCH + bm0 + bb) * G3 + jg;
            gir[bb] = grow[0];
            giz[bb] = grow[512];
            gin[bb] = grow[1024];
        }

        // ---- k-eighth matmul: 24 FFMA2 per k, 64 k ----
        ull accR[8], accZ[8], accN[8];
        #pragma unroll
        for (int bp = 0; bp < 8; bp++) { accR[bp] = 0; accZ[bp] = 0; accN[bp] = 0; }

        #pragma unroll 2
        for (int kk = 0; kk < 64; kk++) {
            int sx = lane ^ (kk & 31);                  // k0 multiple of 32
            ull w0d = dup2(wp[kk * 32 + sx]);
            ull w1d = dup2(wp[512 * 32 + kk * 32 + sx]);
            ull w2d = dup2(wp[1024 * 32 + kk * 32 + sx]);
            const ull* hrow = (const ull*)(h_s + (k0 + kk) * 16);
            #pragma unroll
            for (int bp = 0; bp < 8; bp++) {
                ull h2 = hrow[bp];
                accR[bp] = ffma2(h2, w0d, accR[bp]);
                accZ[bp] = ffma2(h2, w1d, accZ[bp]);
                accN[bp] = ffma2(h2, w2d, accN[bp]);
            }
        }

        // capture h_old (hidden index jg) for my 2 batches before h_s is reused
        float hold0 = h_s[jg * 16 + 2 * warp];
        float hold1 = h_s[jg * 16 + 2 * warp + 1];
        __syncthreads();

        // ---- two-phase cross-warp reduction through scratch overlaid on h_s ----
        // slot layout: sc[(s*24 + g*8 + bp)*32 + lane], s = warp & 3 (4 slots, 24.5 KB)
        ull* sc = (ull*)h_s;
        if (warp >= 4) {
            int s = warp - 4;
            #pragma unroll
            for (int bp = 0; bp < 8; bp++) {
                sc[(s * 24 + bp) * 32 + lane]      = accR[bp];
                sc[(s * 24 + 8 + bp) * 32 + lane]  = accZ[bp];
                sc[(s * 24 + 16 + bp) * 32 + lane] = accN[bp];
            }
        }
        __syncthreads();
        if (warp < 4) {
            int s = warp;
            #pragma unroll
            for (int bp = 0; bp < 8; bp++) {
                int i0 = (s * 24 + bp) * 32 + lane;
                int i1 = (s * 24 + 8 + bp) * 32 + lane;
                int i2 = (s * 24 + 16 + bp) * 32 + lane;
                sc[i0] = fadd2(accR[bp], sc[i0]);
                sc[i1] = fadd2(accZ[bp], sc[i1]);
                sc[i2] = fadd2(accN[bp], sc[i2]);
            }
        }
        __syncthreads();

        // final: each warp sums the 4 slots for its OWN bpair (= warp)
        ull sumR = sc[(0 * 24 + warp) * 32 + lane];
        ull sumZ = sc[(0 * 24 + 8 + warp) * 32 + lane];
        ull sumN = sc[(0 * 24 + 16 + warp) * 32 + lane];
        #pragma unroll
        for (int s = 1; s < 4; s++) {
            sumR = fadd2(sumR, sc[(s * 24 + warp) * 32 + lane]);
            sumZ = fadd2(sumZ, sc[(s * 24 + 8 + warp) * 32 + lane]);
            sumN = fadd2(sumN, sc[(s * 24 + 16 + warp) * 32 + lane]);
        }

        // ---- gates + h update (2 batches per thread) ----
        float rl, rh, zl, zh, nl, nh;
        unpack2(sumR, rl, rh);
        unpack2(sumZ, zl, zh);
        unpack2(sumN, nl, nh);

        float r0  = sigm(gir[0] + rl + brj);
        float zg0 = sigm(giz[0] + zl + bzj);
        float nn0 = tanhf(gin[0] + r0 * (nl + bnj));
        float hnew0 = (1.0f - zg0) * nn0 + zg0 * hold0;
        float out0  = (mask_out && t >= nb0) ? 0.0f : hnew0;

        float r1  = sigm(gir[1] + rh + brj);
        float zg1 = sigm(giz[1] + zh + bzj);
        float nn1 = tanhf(gin[1] + r1 * (nh + bnj));
        float hnew1 = (1.0f - zg1) * nn1 + zg1 * hold1;
        float out1  = (mask_out && t >= nb1) ? 0.0f : hnew1;

        float* wr = (t & 1) ? hbt0 : hbt1;
        __stcg(&wr[jg * BATCH + bm0], hnew0);
        __stcg(&wr[jg * BATCH + bm0 + 1], hnew1);

        // ---- group barrier (release: only the 2 h stores need draining) ----
        if (t < 63) {
            __threadfence();
            __syncthreads();
            if (tid == 0) {
                atomicAdd(&g_ctr[bt], 1);
                int target = (t + 1) * 16;
                while (((volatile int*)g_ctr)[bt] < target) { }
                __threadfence();
            }
            __syncthreads();
        }

        // hs_out stores after the barrier (overlap with reload; drained at kernel end)
        hs_out[((long)t * BATCH + bm0) * 512 + jg]     = out0;
        hs_out[((long)t * BATCH + bm0 + 1) * 512 + jg] = out1;

        if (t < 63) {
            float* rd = (t & 1) ? hbt0 : hbt1;
            #pragma unroll
            for (int it = 0; it < 8; it++) {
                int f = tid + 256 * it;        // 0..2047 float4
                int k = f >> 2;
                int b4 = (f & 3) << 2;
                float4 v = __ldcg((const float4*)(rd + k * BATCH + b0 + b4));
                *(float4*)&h_s[k * 16 + b4] = v;
            }
            __syncthreads();
        }
    }
}

// ---------------- pair kernel ----------------
__global__ __launch_bounds__(256)
void pair_kernel(const float* __restrict__ ca, const float* __restrict__ cb,
                 const float* __restrict__ b1, const float* __restrict__ W2,
                 const float* __restrict__ b2, const float* __restrict__ gu,
                 const int* __restrict__ n_nodes, float* __restrict__ out)
{
    int w    = (blockIdx.x * blockDim.x + threadIdx.x) >> 5;
    int lane = threadIdx.x & 31;
    int b = w / NPAIR;
    int p = w - b * NPAIR;
    int i = 0, rem = p, len = 63;
    while (rem >= len) { rem -= len; len--; i++; }
    int j = i + 1 + rem;

    const float* ra = ca + (long)(i * 128 + b) * HIDDEN;
    const float* rb = cb + (long)(j * 128 + b) * HIDDEN;
    float a0 = 0.0f, a1 = 0.0f;
    #pragma unroll
    for (int kk = 0; kk < 16; kk++) {
        int idx = (kk << 5) + lane;
        float v = ra[idx] + rb[idx] + b1[idx];
        v = fmaxf(v, 0.0f);
        a0 = fmaf(v, W2[idx], a0);
        a1 = fmaf(v, W2[HIDDEN + idx], a1);
    }
    #pragma unroll
    for (int off = 16; off; off >>= 1) {
        a0 += __shfl_down_sync(0xffffffffu, a0, off);
        a1 += __shfl_down_sync(0xffffffffu, a1, off);
    }
    if (lane == 0) {
        int n = n_nodes[b];
        if (i < n && j < n) {
            const float* g = gu + ((long)b * NPAIR + p) * 2;
            float g0 = -logf(-logf(g[0] + 1e-10f) + 1e-10f);
            float g1 = -logf(-logf(g[1] + 1e-10f) + 1e-10f);
            float s0 = a0 + b2[0] + g0;
            float s1 = a1 + b2[1] + g1;
            float val = (s0 >= s1) ? 1.0f : 0.0f;
            out[((long)b * 64 + i) * 64 + j] = val;
            out[((long)b * 64 + j) * 64 + i] = val;
        }
    }
}

// ---------------- launcher ----------------
extern "C" void kernel_launch(void* const* d_in, const int* in_sizes, int n_in,
                              void* d_out, int out_size)
{
    (void)in_sizes; (void)n_in;
    const float* z       = (const float*)d_in[0];
    const int*   n_nodes = (const int*)  d_in[1];
    const float* gu      = (const float*)d_in[3];
    const float* emb     = (const float*)d_in[4];
    const float* pe      = (const float*)d_in[5];
    const float* W_pre   = (const float*)d_in[6];
    const float* b_pre   = (const float*)d_in[7];
    const float* Wih0    = (const float*)d_in[8];
    const float* Whh0    = (const float*)d_in[9];
    const float* bih0    = (const float*)d_in[10];
    const float* bhh0    = (const float*)d_in[11];
    const float* Wih1    = (const float*)d_in[12];
    const float* Whh1    = (const float*)d_in[13];
    const float* bih1    = (const float*)d_in[14];
    const float* bhh1    = (const float*)d_in[15];
    const float* node_W  = (const float*)d_in[16];
    const float* adj_W1  = (const float*)d_in[17];
    const float* adj_b1  = (const float*)d_in[18];
    const float* adj_W2  = (const float*)d_in[19];
    const float* adj_b2  = (const float*)d_in[20];

    float *x, *seq, *gi, *hs0, *hs1, *node, *ca, *cb, *hbt;
    cudaGetSymbolAddress((void**)&x,    g_x);
    cudaGetSymbolAddress((void**)&seq,  g_seq);
    cudaGetSymbolAddress((void**)&gi,   g_gi);
    cudaGetSymbolAddress((void**)&hs0,  g_hs0);
    cudaGetSymbolAddress((void**)&hs1,  g_hs1);
    cudaGetSymbolAddress((void**)&node, g_node);
    cudaGetSymbolAddress((void**)&ca,   g_ca);
    cudaGetSymbolAddress((void**)&cb,   g_cb);
    cudaGetSymbolAddress((void**)&hbt,  g_ht);
    float* hbt0 = hbt;
    float* hbt1 = hbt + HIDDEN * BATCH;

    cudaFuncSetAttribute(gru_persist3, cudaFuncAttributeMaxDynamicSharedMemorySize,
                         GRU_SMEM_BYTES);

    // 1) x = concat(z+pe, emb)                                [launch 1]
    build_x<<<SEQROWS * 512 / 256, 256>>>(z, pe, emb, x);
    // 2) seq = x @ W_pre^T + b_pre ; mask                     [launches 2,3]
    sgemm2<<<dim3(LATENT / 128, SEQROWS / 128), 256>>>(x, 512, W_pre, 512, seq, LATENT, b_pre, 512);
    mask_kernel<<<SEQROWS * LATENT / 256, 256>>>(seq, n_nodes, 8);
    // 3) gi0 = seq @ Wih0^T + bih0                            [launch 4]
    sgemm2<<<dim3(G3 / 128, SEQROWS / 128), 256>>>(seq, LATENT, Wih0, LATENT, gi, G3, bih0, LATENT);
    // 4) GRU layer 0 (persistent, 8-warp k-split)             [launches 5,6 -> ncu -s 5 captures gru]
    zero_ctr<<<1, 32>>>();
    gru_persist3<<<128, 256, GRU_SMEM_BYTES>>>(gi, Whh0, bhh0, hs0, hbt0, hbt1, n_nodes, 0);
    // 5) gi1 = hs0 @ Wih1^T + bih1
    sgemm2<<<dim3(G3 / 128, SEQROWS / 128), 256>>>(hs0, HIDDEN, Wih1, HIDDEN, gi, G3, bih1, HIDDEN);
    // 6) GRU layer 1 (persistent, mask fused into output)
    zero_ctr<<<1, 32>>>();
    gru_persist3<<<128, 256, GRU_SMEM_BYTES>>>(gi, Whh1, bhh1, hs1, hbt0, hbt1, n_nodes, 1);
    // 7) node_emb = rnn_out @ node_W^T  (hs1 already masked)
    sgemm2<<<dim3(HIDDEN / 128, SEQROWS / 128), 256>>>(hs1, HIDDEN, node_W, HIDDEN, node, HIDDEN, nullptr, HIDDEN);
    // 8) pair-MLP per-node halves
    sgemm2<<<dim3(HIDDEN / 128, SEQROWS / 128), 256>>>(node, HIDDEN, adj_W1, 1024, ca, HIDDEN, nullptr, HIDDEN);
    sgemm2<<<dim3(HIDDEN / 128, SEQROWS / 128), 256>>>(node, HIDDEN, adj_W1 + 512, 1024, cb, HIDDEN, nullptr, HIDDEN);
    // 9) adjacency
    cudaMemsetAsync(d_out, 0, (size_t)out_size * sizeof(float));
    pair_kernel<<<(BATCH * NPAIR * 32) / 256, 256>>>(ca, cb, adj_b1, adj_W2, adj_b2,
                                                     gu, n_nodes, (float*)d_out);
}